// round 16
// baseline (speedup 1.0000x reference)
#include <cuda_runtime.h>

// Heston Monte Carlo: 65536 paths x 512 steps.
// Inputs:  d_in[0] = Z_vol  [65536, 512, 2] f32 (only [:,:,0] used)
//          d_in[1] = Z_price[65536, 512]    f32
// Output:  d_out = S [65536,513] f32 followed by V [65536,513] f32
//
// Depth-3 pipelined, 3 smem buffers, ONE block barrier per chunk:
//   iter ck: LOAD chunk ck+3 -> regset ck%3 (freed by last iter's stage)
//            STAGE regset (ck+1)%3 (loaded 2 iters ago -> landed) -> buf (ck+1)%3
//            COMPUTE ck in buf ck%3 (in-place S/V overwrite)
//            BAR
//            STORE ck from buf ck%3
// Hazards: stage->compute separated by the BAR; store->restage of the same
// buffer separated by the NEXT iteration's BAR (3-buffer rotation gives the
// needed slack). Streaming cache ops (__ldcs/__stcs): data touched once.

#define NSTEPS   512
#define NP1      513
#define BATCH    65536
#define TPB      64
#define CHUNK    16
#define NCHUNKS  (NSTEPS / CHUNK)    // 32
#define NBUF     3
#define PITCH    17                  // odd stride -> conflict-free compute reads

__global__ __launch_bounds__(TPB, 4) void heston_kernel(
    const float* __restrict__ zvolx,    // [BATCH][NSTEPS][2] f32, read [..][0]
    const float* __restrict__ zprice,   // [BATCH][NSTEPS]
    float* __restrict__ S_out,          // [BATCH][NP1]
    float* __restrict__ V_out)          // [BATCH][NP1]
{
    __shared__ float sZV[NBUF][TPB * PITCH];  // zv in -> S out (in place)
    __shared__ float sZP[NBUF][TPB * PITCH];  // zp in -> V out (in place)

    const int tid = threadIdx.x;
    const long long pbase  = (long long)blockIdx.x * TPB;
    const long long mypath = pbase + tid;

    // fixed cooperative coords: element i = k*TPB + tid -> row = k*4+crow, col = ccol
    const int crow = tid >> 4;
    const int ccol = tid & 15;

    // model constants
    const float dt       = 1.0f / 512.0f;
    const float sqrt_dt  = 0.04419417382415922f;     // sqrt(1/512)
    const float rho      = -0.7f;
    const float rho_perp = 0.7141428428542850f;      // sqrt(1-rho^2)
    const float V0f      = 0.055225f;                 // 0.235^2
    const float kth_dt   = 0.04f * dt;                // KAPPA*THETA*dt (KAPPA=1)
    const float two_sdt  = 2.0f * sqrt_dt;            // SIGMA_V * sqrt_dt

    // t = 0 column (tiny)
    S_out[mypath * NP1] = 100.0f;
    V_out[mypath * NP1] = V0f;

    // three prefetch register sets
    float azv[CHUNK], azp[CHUNK];
    float bzv[CHUNK], bzp[CHUNK];
    float czv[CHUNK], czp[CHUNK];

    const long long gbase = (pbase + crow) * (long long)NSTEPS + ccol;

    #define LOAD_SET(zvr, zpr, t0)                                           \
        _Pragma("unroll")                                                     \
        for (int k = 0; k < CHUNK; k++) {                                     \
            const long long g = gbase + (long long)(k * 4) * NSTEPS + (t0);   \
            zvr[k] = __ldcs(&zvolx[2 * g]);                                   \
            zpr[k] = __ldcs(&zprice[g]);                                      \
        }

    #define STAGE_SET(zvr, zpr, buf)                                          \
        _Pragma("unroll")                                                     \
        for (int k = 0; k < CHUNK; k++) {                                     \
            const int sidx = (k * 4 + crow) * PITCH + ccol;                   \
            sZV[buf][sidx] = zvr[k];                                          \
            sZP[buf][sidx] = zpr[k];                                          \
        }

    #define COMPUTE_CHUNK(buf)                                                \
        {                                                                     \
            float* myZV = &sZV[buf][tid * PITCH];                             \
            float* myZP = &sZP[buf][tid * PITCH];                             \
            _Pragma("unroll")                                                 \
            for (int c = 0; c < CHUNK; c++) {                                 \
                const float zv = myZV[c];                                     \
                const float zp = myZP[c];                                     \
                const float Vpos = fmaxf(V, 0.0f);                            \
                const float sv   = sqrtf(Vpos);                               \
                float Vnext = fmaf(two_sdt * zv, sv,                          \
                                   fmaf(-dt, Vpos, V + kth_dt));              \
                Vnext = fmaxf(Vnext, 0.0f);                                   \
                const float dB = sqrt_dt * fmaf(rho, zv, rho_perp * zp);      \
                logS = fmaf(sv, dB, fmaf(-0.5f * dt, Vpos, logS));            \
                myZV[c] = 100.0f * __expf(logS);  /* S */                     \
                myZP[c] = Vnext;                  /* V */                     \
                V = Vnext;                                                    \
            }                                                                 \
        }

    #define STORE_CHUNK(buf, t0)                                              \
        {                                                                     \
            _Pragma("unroll")                                                 \
            for (int k = 0; k < CHUNK; k++) {                                 \
                const int sidx = (k * 4 + crow) * PITCH + ccol;               \
                const long long o = (pbase + k * 4 + crow) * (long long)NP1   \
                                    + ((t0) + 1 + ccol);                      \
                __stcs(&S_out[o], sZV[buf][sidx]);                            \
                __stcs(&V_out[o], sZP[buf][sidx]);                            \
            }                                                                 \
        }

    // one pipeline iteration; s0 = ck%3 (compute buf / load regset),
    // s1 = (ck+1)%3 (stage regset -> buf)
    #define ITER(ck, zv0, zp0, zv1, zp1, b0, b1)                              \
        {                                                                     \
            if ((ck) + 3 < NCHUNKS) { LOAD_SET(zv0, zp0, ((ck) + 3) * CHUNK) }\
            if ((ck) + 1 < NCHUNKS) { STAGE_SET(zv1, zp1, b1) }               \
            COMPUTE_CHUNK(b0)                                                 \
            __syncthreads();                                                  \
            STORE_CHUNK(b0, (ck) * CHUNK)                                     \
        }

    // ---- prologue: chunks 0,1,2 -> sets A,B,C; stage chunk0 -> buf0 ----
    LOAD_SET(azv, azp, 0 * CHUNK)
    LOAD_SET(bzv, bzp, 1 * CHUNK)
    LOAD_SET(czv, czp, 2 * CHUNK)
    STAGE_SET(azv, azp, 0)
    __syncthreads();

    float V    = V0f;
    float logS = 0.0f;

    #pragma unroll 1
    for (int base = 0; base < NCHUNKS - 2; base += 3) {   // 0..27 (10 triples)
        ITER(base + 0, azv, azp, bzv, bzp, 0, 1)
        ITER(base + 1, bzv, bzp, czv, czp, 1, 2)
        ITER(base + 2, czv, czp, azv, azp, 2, 0)
    }
    // remainder: chunks 30 (s0=0) and 31 (s0=1)
    ITER(30, azv, azp, bzv, bzp, 0, 1)
    ITER(31, bzv, bzp, czv, czp, 1, 2)

    #undef LOAD_SET
    #undef STAGE_SET
    #undef COMPUTE_CHUNK
    #undef STORE_CHUNK
    #undef ITER
}

extern "C" void kernel_launch(void* const* d_in, const int* in_sizes, int n_in,
                              void* d_out, int out_size) {
    const float* zvolx  = (const float*)d_in[0];
    const float* zprice = (const float*)d_in[1];
    float* S  = (float*)d_out;
    float* Vv = S + (size_t)BATCH * NP1;

    heston_kernel<<<BATCH / TPB, TPB>>>(zvolx, zprice, S, Vv);
}

// round 17
// speedup vs baseline: 1.1117x; 1.1117x over previous
#include <cuda_runtime.h>

// Heston Monte Carlo: 65536 paths x 512 steps.
// Inputs:  d_in[0] = Z_vol  [65536, 512, 2] f32 (only [:,:,0] used)
//          d_in[1] = Z_price[65536, 512]    f32
// Output:  d_out = S [65536,513] f32 followed by V [65536,513] f32
//
// Champion R15 skeleton (depth-2 register prefetch, CHUNK=16, TPB=64) with a
// 3rd smem buffer so only ONE block barrier per chunk is needed:
//   iter ck: LOAD chunk ck+2 -> regset ck%2 (freed by last iter's stage)
//            STAGE regset (ck+1)%2 (chunk ck+1, loaded a full iter ago) -> buf (ck+1)%3
//            COMPUTE chunk ck in buf ck%3 (in-place S/V overwrite)
//            BAR
//            STORE chunk ck from buf ck%3   (overlaps next iter's LOAD/STAGE/COMPUTE)
// Store-read -> restage of the same buffer is separated by the NEXT barrier,
// which the 3-buffer rotation guarantees.

#define NSTEPS   512
#define NP1      513
#define BATCH    65536
#define TPB      64
#define CHUNK    16
#define NCHUNKS  (NSTEPS / CHUNK)    // 32
#define NBUF     3
#define PITCH    17                  // odd stride -> conflict-free compute reads

__global__ __launch_bounds__(TPB, 8) void heston_kernel(
    const float* __restrict__ zvolx,    // [BATCH][NSTEPS][2] f32, read [..][0]
    const float* __restrict__ zprice,   // [BATCH][NSTEPS]
    float* __restrict__ S_out,          // [BATCH][NP1]
    float* __restrict__ V_out)          // [BATCH][NP1]
{
    __shared__ float sZV[NBUF][TPB * PITCH];  // zv in -> S out (in place)
    __shared__ float sZP[NBUF][TPB * PITCH];  // zp in -> V out (in place)

    const int tid = threadIdx.x;
    const long long pbase  = (long long)blockIdx.x * TPB;
    const long long mypath = pbase + tid;

    // fixed cooperative coords: element i = k*TPB + tid -> row = k*4+crow, col = ccol
    const int crow = tid >> 4;
    const int ccol = tid & 15;

    // model constants
    const float dt       = 1.0f / 512.0f;
    const float sqrt_dt  = 0.04419417382415922f;     // sqrt(1/512)
    const float rho      = -0.7f;
    const float rho_perp = 0.7141428428542850f;      // sqrt(1-rho^2)
    const float V0f      = 0.055225f;                 // 0.235^2
    const float kth_dt   = 0.04f * dt;                // KAPPA*THETA*dt (KAPPA=1)
    const float two_sdt  = 2.0f * sqrt_dt;            // SIGMA_V * sqrt_dt

    // t = 0 column (tiny, negligible)
    S_out[mypath * NP1] = 100.0f;
    V_out[mypath * NP1] = V0f;

    float azv[CHUNK], azp[CHUNK];   // regset A
    float bzv[CHUNK], bzp[CHUNK];   // regset B

    const long long gbase = (pbase + crow) * (long long)NSTEPS + ccol;

    #define LOAD_SET(zvr, zpr, t0)                                           \
        _Pragma("unroll")                                                     \
        for (int k = 0; k < CHUNK; k++) {                                     \
            const long long g = gbase + (long long)(k * 4) * NSTEPS + (t0);   \
            zvr[k] = zvolx[2 * g];                                            \
            zpr[k] = zprice[g];                                               \
        }

    #define STAGE_SET(zvr, zpr, buf)                                          \
        _Pragma("unroll")                                                     \
        for (int k = 0; k < CHUNK; k++) {                                     \
            const int sidx = (k * 4 + crow) * PITCH + ccol;                   \
            sZV[buf][sidx] = zvr[k];                                          \
            sZP[buf][sidx] = zpr[k];                                          \
        }

    #define COMPUTE_CHUNK(buf)                                                \
        {                                                                     \
            float* myZV = &sZV[buf][tid * PITCH];                             \
            float* myZP = &sZP[buf][tid * PITCH];                             \
            _Pragma("unroll")                                                 \
            for (int c = 0; c < CHUNK; c++) {                                 \
                const float zv = myZV[c];                                     \
                const float zp = myZP[c];                                     \
                const float Vpos = fmaxf(V, 0.0f);                            \
                const float sv   = sqrtf(Vpos);                               \
                float Vnext = fmaf(two_sdt * zv, sv,                          \
                                   fmaf(-dt, Vpos, V + kth_dt));              \
                Vnext = fmaxf(Vnext, 0.0f);                                   \
                const float dB = sqrt_dt * fmaf(rho, zv, rho_perp * zp);      \
                logS = fmaf(sv, dB, fmaf(-0.5f * dt, Vpos, logS));            \
                myZV[c] = 100.0f * __expf(logS);  /* S */                     \
                myZP[c] = Vnext;                  /* V */                     \
                V = Vnext;                                                    \
            }                                                                 \
        }

    #define STORE_CHUNK(buf, t0)                                              \
        {                                                                     \
            _Pragma("unroll")                                                 \
            for (int k = 0; k < CHUNK; k++) {                                 \
                const int sidx = (k * 4 + crow) * PITCH + ccol;               \
                const long long o = (pbase + k * 4 + crow) * (long long)NP1   \
                                    + ((t0) + 1 + ccol);                      \
                S_out[o] = sZV[buf][sidx];                                    \
                V_out[o] = sZP[buf][sidx];                                    \
            }                                                                 \
        }

    // one pipeline iteration: load into (zv0,zp0), stage (zv1,zp1) -> b1,
    // compute b0, BAR, store b0. ONE barrier per chunk.
    #define ITER(ck, zv0, zp0, zv1, zp1, b0, b1)                              \
        {                                                                     \
            if ((ck) + 2 < NCHUNKS) { LOAD_SET(zv0, zp0, ((ck) + 2) * CHUNK) }\
            if ((ck) + 1 < NCHUNKS) { STAGE_SET(zv1, zp1, b1) }               \
            COMPUTE_CHUNK(b0)                                                 \
            __syncthreads();                                                  \
            STORE_CHUNK(b0, (ck) * CHUNK)                                     \
        }

    // ---- prologue: A<-chunk0, B<-chunk1; stage A -> buf0 ----
    LOAD_SET(azv, azp, 0 * CHUNK)
    LOAD_SET(bzv, bzp, 1 * CHUNK)
    STAGE_SET(azv, azp, 0)
    __syncthreads();

    float V    = V0f;
    float logS = 0.0f;

    // pattern has period 6 (sets alternate mod 2, buffers rotate mod 3)
    #pragma unroll 1
    for (int base = 0; base < 30; base += 6) {   // ck = 0..29
        ITER(base + 0, azv, azp, bzv, bzp, 0, 1)
        ITER(base + 1, bzv, bzp, azv, azp, 1, 2)
        ITER(base + 2, azv, azp, bzv, bzp, 2, 0)
        ITER(base + 3, bzv, bzp, azv, azp, 0, 1)
        ITER(base + 4, azv, azp, bzv, bzp, 1, 2)
        ITER(base + 5, bzv, bzp, azv, azp, 2, 0)
    }
    // remainder: ck = 30 (set A, buf 0), ck = 31 (set B, buf 1)
    ITER(30, azv, azp, bzv, bzp, 0, 1)
    ITER(31, bzv, bzp, azv, azp, 1, 2)

    #undef LOAD_SET
    #undef STAGE_SET
    #undef COMPUTE_CHUNK
    #undef STORE_CHUNK
    #undef ITER
}

extern "C" void kernel_launch(void* const* d_in, const int* in_sizes, int n_in,
                              void* d_out, int out_size) {
    const float* zvolx  = (const float*)d_in[0];
    const float* zprice = (const float*)d_in[1];
    float* S  = (float*)d_out;
    float* Vv = S + (size_t)BATCH * NP1;

    heston_kernel<<<BATCH / TPB, TPB>>>(zvolx, zprice, S, Vv);
}